// round 3
// baseline (speedup 1.0000x reference)
#include <cuda_runtime.h>
#include <stdint.h>

#define OUTPUT_DIM 64
#define NB_CTRL_SIG 16
#define FULL_DIM (OUTPUT_DIM * NB_CTRL_SIG)   // 1024
#define VEC 4                                 // float4 per slot
#define SLOTS_PER_ROW (OUTPUT_DIM / VEC)      // 16
#define ROW_F4 (FULL_DIM / VEC)               // 256 float4 per input row
#define UNROLL 8

// out[b, j] = full_input[b, idx[b]*64 + j]
// Each thread handles UNROLL float4 slots strided by the total thread count:
// per-slot coalescing identical to 1-slot version, MLP = UNROLL.
__global__ void multiplexer_kernel(const float4* __restrict__ full_input,
                                   const int* __restrict__ indices,
                                   float4* __restrict__ out,
                                   int total_slots, int stride_slots) {
    int s0 = blockIdx.x * blockDim.x + threadIdx.x;
    int sl = s0 + (UNROLL - 1) * stride_slots;   // last slot this thread owns

    if (sl < total_slots) {
        // fast path (always taken for this problem size: total divides evenly)
        int s[UNROLL];
        #pragma unroll
        for (int u = 0; u < UNROLL; u++) s[u] = s0 + u * stride_slots;

        int idx[UNROLL];
        #pragma unroll
        for (int u = 0; u < UNROLL; u++) idx[u] = __ldg(&indices[s[u] >> 4]);

        float4 v[UNROLL];
        #pragma unroll
        for (int u = 0; u < UNROLL; u++) {
            int b = s[u] >> 4;
            int j = s[u] & 15;
            v[u] = __ldg(&full_input[(size_t)b * ROW_F4 + idx[u] * SLOTS_PER_ROW + j]);
        }

        #pragma unroll
        for (int u = 0; u < UNROLL; u++) out[s[u]] = v[u];
    } else {
        #pragma unroll
        for (int u = 0; u < UNROLL; u++) {
            int s = s0 + u * stride_slots;
            if (s < total_slots) {
                int b = s >> 4, j = s & 15;
                int i = __ldg(&indices[b]);
                out[s] = __ldg(&full_input[(size_t)b * ROW_F4 + i * SLOTS_PER_ROW + j]);
            }
        }
    }
}

extern "C" void kernel_launch(void* const* d_in, const int* in_sizes, int n_in,
                              void* d_out, int out_size) {
    const float4* full_input = (const float4*)d_in[0];
    const int*    indices    = (const int*)d_in[1];
    float4*       out        = (float4*)d_out;

    int batch       = in_sizes[1];                  // 262144
    int total_slots = batch * SLOTS_PER_ROW;        // 4,194,304 float4 slots
    int block       = 256;
    int threads     = (total_slots + UNROLL - 1) / UNROLL;  // 524,288
    int grid        = (threads + block - 1) / block;        // 2048
    int stride      = grid * block;                 // slot stride between legs

    multiplexer_kernel<<<grid, block>>>(full_input, indices, out, total_slots, stride);
}